// round 2
// baseline (speedup 1.0000x reference)
#include <cuda_runtime.h>
#include <cstdint>

#define N_HEADC 16
#define N_KVC 4
#define D_MODELC 2048
#define D_HEADC 128
#define BATCHC 2
#define SEQC 2048
#define M_ROWS (BATCHC*SEQC)           // 4096
#define Q_INNERC (N_HEADC*D_HEADC)     // 2048
#define KV_INNERC (N_KVC*D_HEADC)      // 512

// ---------------- scratch (device globals: allocation-free) ----------------
__device__ float g_Q[(size_t)BATCHC*N_HEADC*SEQC*D_HEADC];   // [b,h,s,d]
__device__ float g_K[(size_t)BATCHC*N_KVC*SEQC*D_HEADC];     // [b,kh,s,d]
__device__ float g_V[(size_t)BATCHC*N_KVC*SEQC*D_HEADC];
__device__ float g_AO[(size_t)M_ROWS*Q_INNERC];              // [b,s,h,d]
__device__ int   g_flags[BATCHC*32*32];                      // per 64x64 mask tile: any-zero?

// ---------------- helpers ----------------
__device__ __forceinline__ unsigned f2tf32(float x) {
    unsigned u;
    asm("cvt.rna.tf32.f32 %0, %1;" : "=r"(u) : "f"(x));
    return u;
}
__device__ __forceinline__ float ex2(float x) {
    float y;
    asm("ex2.approx.f32 %0, %1;" : "=f"(y) : "f"(x));
    return y;
}
__device__ __forceinline__ void mma_tf32(float* d, const unsigned* a, const unsigned* b) {
    asm volatile(
        "mma.sync.aligned.m16n8k8.row.col.f32.tf32.tf32.f32 "
        "{%0,%1,%2,%3}, {%4,%5,%6,%7}, {%8,%9}, {%0,%1,%2,%3};"
        : "+f"(d[0]), "+f"(d[1]), "+f"(d[2]), "+f"(d[3])
        : "r"(a[0]), "r"(a[1]), "r"(a[2]), "r"(a[3]), "r"(b[0]), "r"(b[1]));
}

// ---------------- mask tile prepass ----------------
__global__ __launch_bounds__(128)
void mask_scan_kernel(const int* __restrict__ mask) {
    const int kt = blockIdx.x, qt = blockIdx.y, b = blockIdx.z;
    const int tid = threadIdx.x;
    int any0 = 0;
#pragma unroll
    for (int i = 0; i < 8; i++) {
        int idx = i * 128 + tid;           // 1024 int4 = 64x64 ints
        int r = idx >> 4;                  // 16 int4 per row
        int c4 = (idx & 15) << 2;
        const int4 v = *reinterpret_cast<const int4*>(
            mask + ((size_t)b * SEQC + qt * 64 + r) * SEQC + kt * 64 + c4);
        if (!(v.x && v.y && v.z && v.w)) any0 = 1;
    }
    any0 = __syncthreads_or(any0);
    if (tid == 0) g_flags[(b * 32 + qt) * 32 + kt] = any0;
}

// ---------------- tf32 GEMM: C = A[M,K] * W[N,K]^T + bias ----------------
// mode 0: C row-major [M, gridDim.x*128]
// mode 1: head layout: m=(b,s), n=(h,d) -> C[((b*H+h)*SEQ+s)*128+d]
__global__ __launch_bounds__(256)
void gemm_tf32_kernel(const float* __restrict__ A, const float* __restrict__ W,
                      const float* __restrict__ bias, float* __restrict__ C,
                      int K, int mode, int H) {
    __shared__ unsigned As[128][36];   // stride 36 (=4 mod 32): conflict-free frag loads
    __shared__ unsigned Bs[128][36];
    const int tid = threadIdx.x;
    const int warp = tid >> 5, lane = tid & 31;
    const int g = lane >> 2, t = lane & 3;
    const int wm = warp >> 2, wn = warp & 3;   // 2x4 warp grid: 64x32 warp tile
    const int rowBase = blockIdx.y * 128;
    const int colBase = blockIdx.x * 128;

    float acc[4][4][4];
#pragma unroll
    for (int i = 0; i < 4; i++)
#pragma unroll
        for (int j = 0; j < 4; j++)
#pragma unroll
            for (int q = 0; q < 4; q++) acc[i][j][q] = 0.f;

    for (int k0 = 0; k0 < K; k0 += 32) {
#pragma unroll
        for (int i = 0; i < 4; i++) {
            int idx = i * 256 + tid;
            int r = idx >> 3;
            int c4 = (idx & 7) << 2;
            float4 va = *reinterpret_cast<const float4*>(A + (size_t)(rowBase + r) * K + k0 + c4);
            As[r][c4 + 0] = f2tf32(va.x); As[r][c4 + 1] = f2tf32(va.y);
            As[r][c4 + 2] = f2tf32(va.z); As[r][c4 + 3] = f2tf32(va.w);
            float4 vb = *reinterpret_cast<const float4*>(W + (size_t)(colBase + r) * K + k0 + c4);
            Bs[r][c4 + 0] = f2tf32(vb.x); Bs[r][c4 + 1] = f2tf32(vb.y);
            Bs[r][c4 + 2] = f2tf32(vb.z); Bs[r][c4 + 3] = f2tf32(vb.w);
        }
        __syncthreads();
#pragma unroll
        for (int kk = 0; kk < 32; kk += 8) {
            unsigned a[4][4], b[4][2];
#pragma unroll
            for (int mt = 0; mt < 4; mt++) {
                int r = wm * 64 + mt * 16;
                a[mt][0] = As[r + g][kk + t];
                a[mt][1] = As[r + g + 8][kk + t];
                a[mt][2] = As[r + g][kk + t + 4];
                a[mt][3] = As[r + g + 8][kk + t + 4];
            }
#pragma unroll
            for (int nt = 0; nt < 4; nt++) {
                int c = wn * 32 + nt * 8 + g;
                b[nt][0] = Bs[c][kk + t];
                b[nt][1] = Bs[c][kk + t + 4];
            }
#pragma unroll
            for (int mt = 0; mt < 4; mt++)
#pragma unroll
                for (int nt = 0; nt < 4; nt++)
                    mma_tf32(acc[mt][nt], a[mt], b[nt]);
        }
        __syncthreads();
    }

    // epilogue
    const int Ntot = gridDim.x * 128;
#pragma unroll
    for (int mt = 0; mt < 4; mt++) {
#pragma unroll
        for (int nt = 0; nt < 4; nt++) {
            int col0 = colBase + wn * 32 + nt * 8 + 2 * t;
            float b0 = bias[col0], b1 = bias[col0 + 1];
#pragma unroll
            for (int half = 0; half < 2; half++) {
                int row = rowBase + wm * 64 + mt * 16 + g + half * 8;
                float v0 = acc[mt][nt][half * 2 + 0] + b0;
                float v1 = acc[mt][nt][half * 2 + 1] + b1;
                if (mode == 0) {
                    size_t base = (size_t)row * Ntot + col0;
                    C[base] = v0; C[base + 1] = v1;
                } else {
                    int b_ = row >> 11, s_ = row & (SEQC - 1);
                    int h0 = col0 >> 7, d0 = col0 & (D_HEADC - 1);
                    size_t o0 = (((size_t)(b_ * H + h0)) * SEQC + s_) * D_HEADC + d0;
                    C[o0] = v0; C[o0 + 1] = v1;
                }
            }
        }
    }
}

// ---------------- flash attention (tf32) ----------------
#define FSTRIDE 132   // 128 + 4 (stride = 4 mod 32)
#define PSTRIDE 68    // 64 + 4
#define FLASH_SMEM ((3*64*FSTRIDE + 4*16*PSTRIDE) * 4)   // 118784 B

__global__ __launch_bounds__(128)
void flash_kernel(const int* __restrict__ mask) {
    extern __shared__ unsigned sh[];
    unsigned* Qs = sh;                        // [64][132]
    unsigned* Ks = Qs + 64 * FSTRIDE;         // [64][132]
    unsigned* Vs = Ks + 64 * FSTRIDE;         // [64][132]
    unsigned* Ps = Vs + 64 * FSTRIDE;         // [4 warps][16][68]

    const int qt = blockIdx.x, h = blockIdx.y, b = blockIdx.z;
    const int kh = h >> 2;                    // N_REP = 4
    const int tid = threadIdx.x;
    const int warp = tid >> 5, lane = tid & 31;
    const int g = lane >> 2, t = lane & 3;
    unsigned* Pw = Ps + warp * 16 * PSTRIDE;

    const float QSCALE = 0.088388347648318447f * 1.4426950408889634f; // (1/sqrt(128))*log2(e)
    const float* Qg = g_Q + (((size_t)(b * N_HEADC + h)) * SEQC + qt * 64) * D_HEADC;
    const float* Kg = g_K + (((size_t)(b * N_KVC + kh)) * SEQC) * D_HEADC;
    const float* Vg = g_V + (((size_t)(b * N_KVC + kh)) * SEQC) * D_HEADC;

    // load Q tile (scaled into log2 domain)
#pragma unroll
    for (int i = 0; i < 16; i++) {
        int idx = i * 128 + tid;
        int r = idx >> 5;
        int c4 = (idx & 31) << 2;
        float4 v = *reinterpret_cast<const float4*>(Qg + (size_t)r * D_HEADC + c4);
        Qs[r * FSTRIDE + c4 + 0] = f2tf32(v.x * QSCALE);
        Qs[r * FSTRIDE + c4 + 1] = f2tf32(v.y * QSCALE);
        Qs[r * FSTRIDE + c4 + 2] = f2tf32(v.z * QSCALE);
        Qs[r * FSTRIDE + c4 + 3] = f2tf32(v.w * QSCALE);
    }

    float m0 = -1e30f, m1 = -1e30f, l0 = 0.f, l1 = 0.f;
    float o[16][4];
#pragma unroll
    for (int i = 0; i < 16; i++)
#pragma unroll
        for (int j = 0; j < 4; j++) o[i][j] = 0.f;

    for (int kt = 0; kt < 32; kt++) {
        __syncthreads();   // previous iter's K/V + P usage done
        const float* Kt = Kg + (size_t)kt * 64 * D_HEADC;
        const float* Vt = Vg + (size_t)kt * 64 * D_HEADC;
#pragma unroll
        for (int i = 0; i < 16; i++) {
            int idx = i * 128 + tid;
            int r = idx >> 5;
            int c4 = (idx & 31) << 2;
            float4 vk = *reinterpret_cast<const float4*>(Kt + (size_t)r * D_HEADC + c4);
            Ks[r * FSTRIDE + c4 + 0] = f2tf32(vk.x);
            Ks[r * FSTRIDE + c4 + 1] = f2tf32(vk.y);
            Ks[r * FSTRIDE + c4 + 2] = f2tf32(vk.z);
            Ks[r * FSTRIDE + c4 + 3] = f2tf32(vk.w);
            float4 vv = *reinterpret_cast<const float4*>(Vt + (size_t)r * D_HEADC + c4);
            Vs[r * FSTRIDE + c4 + 0] = f2tf32(vv.x);
            Vs[r * FSTRIDE + c4 + 1] = f2tf32(vv.y);
            Vs[r * FSTRIDE + c4 + 2] = f2tf32(vv.z);
            Vs[r * FSTRIDE + c4 + 3] = f2tf32(vv.w);
        }
        __syncthreads();

        // S = Q * K^T (already log2-scaled), warp computes 16 q-rows x 64 k-cols
        float s[8][4];
#pragma unroll
        for (int i = 0; i < 8; i++)
#pragma unroll
            for (int j = 0; j < 4; j++) s[i][j] = 0.f;

        const int qr = warp * 16;
#pragma unroll
        for (int ks = 0; ks < 16; ks++) {
            int kb = ks * 8;
            unsigned a[4];
            a[0] = Qs[(qr + g) * FSTRIDE + kb + t];
            a[1] = Qs[(qr + g + 8) * FSTRIDE + kb + t];
            a[2] = Qs[(qr + g) * FSTRIDE + kb + t + 4];
            a[3] = Qs[(qr + g + 8) * FSTRIDE + kb + t + 4];
#pragma unroll
            for (int nt = 0; nt < 8; nt++) {
                unsigned bb[2];
                bb[0] = Ks[(nt * 8 + g) * FSTRIDE + kb + t];
                bb[1] = Ks[(nt * 8 + g) * FSTRIDE + kb + t + 4];
                mma_tf32(s[nt], a, bb);
            }
        }

        // masking (fast path skips entirely when tile is all ones)
        if (g_flags[(b * 32 + qt) * 32 + kt]) {
            int qr0 = qt * 64 + warp * 16 + g;
            const int* mrow0 = mask + ((size_t)b * SEQC + qr0) * SEQC;
            const int* mrow1 = mrow0 + 8 * SEQC;
#pragma unroll
            for (int nt = 0; nt < 8; nt++) {
                int kc = kt * 64 + nt * 8 + 2 * t;
                if (mrow0[kc] == 0)     s[nt][0] = -1e30f;
                if (mrow0[kc + 1] == 0) s[nt][1] = -1e30f;
                if (mrow1[kc] == 0)     s[nt][2] = -1e30f;
                if (mrow1[kc + 1] == 0) s[nt][3] = -1e30f;
            }
        }

        // online softmax (base 2)
        float mx0 = -1e30f, mx1 = -1e30f;
#pragma unroll
        for (int nt = 0; nt < 8; nt++) {
            mx0 = fmaxf(mx0, fmaxf(s[nt][0], s[nt][1]));
            mx1 = fmaxf(mx1, fmaxf(s[nt][2], s[nt][3]));
        }
        mx0 = fmaxf(mx0, __shfl_xor_sync(0xffffffffu, mx0, 1));
        mx0 = fmaxf(mx0, __shfl_xor_sync(0xffffffffu, mx0, 2));
        mx1 = fmaxf(mx1, __shfl_xor_sync(0xffffffffu, mx1, 1));
        mx1 = fmaxf(mx1, __shfl_xor_sync(0xffffffffu, mx1, 2));
        float nm0 = fmaxf(m0, mx0), nm1 = fmaxf(m1, mx1);
        float c0 = ex2(m0 - nm0), c1 = ex2(m1 - nm1);
        m0 = nm0; m1 = nm1;

        float ps0 = 0.f, ps1 = 0.f;
#pragma unroll
        for (int nt = 0; nt < 8; nt++) {
            float p00 = ex2(s[nt][0] - nm0);
            float p01 = ex2(s[nt][1] - nm0);
            float p10 = ex2(s[nt][2] - nm1);
            float p11 = ex2(s[nt][3] - nm1);
            ps0 += p00 + p01;
            ps1 += p10 + p11;
            int col = nt * 8 + 2 * t;
            Pw[g * PSTRIDE + col]           = f2tf32(p00);
            Pw[g * PSTRIDE + col + 1]       = f2tf32(p01);
            Pw[(g + 8) * PSTRIDE + col]     = f2tf32(p10);
            Pw[(g + 8) * PSTRIDE + col + 1] = f2tf32(p11);
        }
        ps0 += __shfl_xor_sync(0xffffffffu, ps0, 1);
        ps0 += __shfl_xor_sync(0xffffffffu, ps0, 2);
        ps1 += __shfl_xor_sync(0xffffffffu, ps1, 1);
        ps1 += __shfl_xor_sync(0xffffffffu, ps1, 2);
        l0 = l0 * c0 + ps0;
        l1 = l1 * c1 + ps1;
#pragma unroll
        for (int nt = 0; nt < 16; nt++) {
            o[nt][0] *= c0; o[nt][1] *= c0;
            o[nt][2] *= c1; o[nt][3] *= c1;
        }
        __syncwarp();

        // O += P * V
#pragma unroll
        for (int ks = 0; ks < 8; ks++) {
            int kb = ks * 8;
            unsigned a[4];
            a[0] = Pw[g * PSTRIDE + kb + t];
            a[1] = Pw[(g + 8) * PSTRIDE + kb + t];
            a[2] = Pw[g * PSTRIDE + kb + t + 4];
            a[3] = Pw[(g + 8) * PSTRIDE + kb + t + 4];
#pragma unroll
            for (int nt = 0; nt < 16; nt++) {
                unsigned bb[2];
                bb[0] = Vs[(kb + t) * FSTRIDE + nt * 8 + g];
                bb[1] = Vs[(kb + t + 4) * FSTRIDE + nt * 8 + g];
                mma_tf32(o[nt], a, bb);
            }
        }
    }

    // epilogue: normalize + write to [b,s,h,d]
    float inv0 = 1.0f / l0, inv1 = 1.0f / l1;
    int s0 = qt * 64 + warp * 16 + g;
#pragma unroll
    for (int nt = 0; nt < 16; nt++) {
        int d0 = nt * 8 + 2 * t;
        size_t base0 = (((size_t)b * SEQC + s0) * N_HEADC + h) * D_HEADC + d0;
        size_t base1 = (((size_t)b * SEQC + s0 + 8) * N_HEADC + h) * D_HEADC + d0;
        g_AO[base0] = o[nt][0] * inv0; g_AO[base0 + 1] = o[nt][1] * inv0;
        g_AO[base1] = o[nt][2] * inv1; g_AO[base1 + 1] = o[nt][3] * inv1;
    }
}

// ---------------- launch ----------------
extern "C" void kernel_launch(void* const* d_in, const int* in_sizes, int n_in,
                              void* d_out, int out_size) {
    const float* hidden = (const float*)d_in[0];
    const int*   mask   = (const int*)d_in[1];
    const float* Wq = (const float*)d_in[2];
    const float* bq = (const float*)d_in[3];
    const float* Wk = (const float*)d_in[4];
    const float* bk = (const float*)d_in[5];
    const float* Wv = (const float*)d_in[6];
    const float* bv = (const float*)d_in[7];
    const float* Wo = (const float*)d_in[8];
    const float* bo = (const float*)d_in[9];
    float* out = (float*)d_out;

    void *pQ, *pK, *pV, *pAO;
    cudaGetSymbolAddress(&pQ, g_Q);
    cudaGetSymbolAddress(&pK, g_K);
    cudaGetSymbolAddress(&pV, g_V);
    cudaGetSymbolAddress(&pAO, g_AO);

    cudaFuncSetAttribute(flash_kernel, cudaFuncAttributeMaxDynamicSharedMemorySize, FLASH_SMEM);

    mask_scan_kernel<<<dim3(32, 32, BATCHC), 128>>>(mask);
    gemm_tf32_kernel<<<dim3(Q_INNERC / 128, M_ROWS / 128), 256>>>(
        hidden, Wq, bq, (float*)pQ, D_MODELC, 1, N_HEADC);
    gemm_tf32_kernel<<<dim3(KV_INNERC / 128, M_ROWS / 128), 256>>>(
        hidden, Wk, bk, (float*)pK, D_MODELC, 1, N_KVC);
    gemm_tf32_kernel<<<dim3(KV_INNERC / 128, M_ROWS / 128), 256>>>(
        hidden, Wv, bv, (float*)pV, D_MODELC, 1, N_KVC);
    flash_kernel<<<dim3(32, N_HEADC, BATCHC), 128, FLASH_SMEM>>>(mask);
    gemm_tf32_kernel<<<dim3(Q_INNERC / 128, M_ROWS / 128), 256>>>(
        (const float*)pAO, Wo, bo, out, Q_INNERC, 0, 0);
}

// round 4
// speedup vs baseline: 1.4626x; 1.4626x over previous
#include <cuda_runtime.h>
#include <cstdint>

#define N_HEADC 16
#define N_KVC 4
#define D_MODELC 2048
#define D_HEADC 128
#define BATCHC 2
#define SEQC 2048
#define M_ROWS (BATCHC*SEQC)           // 4096
#define Q_INNERC (N_HEADC*D_HEADC)     // 2048
#define KV_INNERC (N_KVC*D_HEADC)      // 512

// ---------------- scratch (device globals: allocation-free) ----------------
__device__ float g_Q[(size_t)BATCHC*N_HEADC*SEQC*D_HEADC];   // [b,h,s,d]
__device__ float g_K[(size_t)BATCHC*N_KVC*SEQC*D_HEADC];     // [b,kh,s,d]
__device__ float g_V[(size_t)BATCHC*N_KVC*SEQC*D_HEADC];
__device__ float g_AO[(size_t)M_ROWS*Q_INNERC];              // [b,s,h,d]
__device__ int   g_flags[BATCHC*32*32];                      // per 64x64 mask tile: any-zero?

// ---------------- helpers ----------------
__device__ __forceinline__ unsigned f2tf32(float x) {
    unsigned u;
    asm("cvt.rna.tf32.f32 %0, %1;" : "=r"(u) : "f"(x));
    return u;
}
__device__ __forceinline__ float ex2(float x) {
    float y;
    asm("ex2.approx.f32 %0, %1;" : "=f"(y) : "f"(x));
    return y;
}
__device__ __forceinline__ void mma_tf32(float* d, const unsigned* a, const unsigned* b) {
    asm volatile(
        "mma.sync.aligned.m16n8k8.row.col.f32.tf32.tf32.f32 "
        "{%0,%1,%2,%3}, {%4,%5,%6,%7}, {%8,%9}, {%0,%1,%2,%3};"
        : "+f"(d[0]), "+f"(d[1]), "+f"(d[2]), "+f"(d[3])
        : "r"(a[0]), "r"(a[1]), "r"(a[2]), "r"(a[3]), "r"(b[0]), "r"(b[1]));
}
__device__ __forceinline__ void cpa16(float* dst_smem, const float* src) {
    unsigned d = (unsigned)__cvta_generic_to_shared(dst_smem);
    asm volatile("cp.async.cg.shared.global [%0], [%1], 16;\n" :: "r"(d), "l"(src));
}
#define CP_COMMIT() asm volatile("cp.async.commit_group;\n" ::: "memory")
#define CP_WAIT0()  asm volatile("cp.async.wait_group 0;\n" ::: "memory")

// ---------------- mask tile prepass ----------------
__global__ __launch_bounds__(128)
void mask_scan_kernel(const int* __restrict__ mask) {
    const int kt = blockIdx.x, qt = blockIdx.y, b = blockIdx.z;
    const int tid = threadIdx.x;
    int any0 = 0;
#pragma unroll
    for (int i = 0; i < 8; i++) {
        int idx = i * 128 + tid;
        int r = idx >> 4;
        int c4 = (idx & 15) << 2;
        const int4 v = *reinterpret_cast<const int4*>(
            mask + ((size_t)b * SEQC + qt * 64 + r) * SEQC + kt * 64 + c4);
        if (!(v.x && v.y && v.z && v.w)) any0 = 1;
    }
    any0 = __syncthreads_or(any0);
    if (tid == 0) g_flags[(b * 32 + qt) * 32 + kt] = any0;
}

// ---------------- pipelined tf32 GEMM (cp.async double-buffered) ----------------
// mode 1: fused QKV. blockIdx.x 0-15 -> Q, 16-19 -> K, 20-23 -> V; head-major out.
// mode 0: O proj. out row-major [M, 2048].
#define GSTR 36
#define GEMM_SMEM (2*2*128*GSTR*4)   // 73728 B

__global__ __launch_bounds__(256, 2)
void gemm_pipe_kernel(const float* __restrict__ A,
                      const float* __restrict__ Wq, const float* __restrict__ bq,
                      const float* __restrict__ Wk, const float* __restrict__ bk,
                      const float* __restrict__ Wv, const float* __restrict__ bv,
                      float* outQ, float* outK, float* outV, int mode) {
    extern __shared__ float sm[];
    float* As = sm;                    // [2][128][GSTR]
    float* Bs = sm + 2 * 128 * GSTR;   // [2][128][GSTR]

    const int tid = threadIdx.x;
    const int warp = tid >> 5, lane = tid & 31;
    const int g = lane >> 2, t = lane & 3;
    const int wm = warp >> 2, wn = warp & 3;       // 2x4 warps: 64x32 tiles
    const int rowBase = blockIdx.y * 128;
    const int bx = blockIdx.x;

    const float* W; const float* bias; float* outP; int colOff; int H;
    if (mode == 0)       { W = Wq; bias = bq; outP = outQ; colOff = bx * 128;        H = 0;  }
    else if (bx < 16)    { W = Wq; bias = bq; outP = outQ; colOff = bx * 128;        H = 16; }
    else if (bx < 20)    { W = Wk; bias = bk; outP = outK; colOff = (bx - 16) * 128; H = 4;  }
    else                 { W = Wv; bias = bv; outP = outV; colOff = (bx - 20) * 128; H = 4;  }

    const int K = D_MODELC;            // 2048 for both passes
    const int NT = K / 32;             // 64 k-tiles

    float acc[4][4][4];
#pragma unroll
    for (int i = 0; i < 4; i++)
#pragma unroll
        for (int j = 0; j < 4; j++)
#pragma unroll
            for (int q = 0; q < 4; q++) acc[i][j][q] = 0.f;

    // prologue: stage 0
    {
#pragma unroll
        for (int i = 0; i < 4; i++) {
            int chunk = i * 256 + tid;         // 1024 chunks of 16B
            int r = chunk >> 3, c4 = (chunk & 7) << 2;
            cpa16(&As[(size_t)r * GSTR + c4], A + (size_t)(rowBase + r) * K + c4);
            cpa16(&Bs[(size_t)r * GSTR + c4], W + (size_t)(colOff + r) * K + c4);
        }
        CP_COMMIT();
    }

    for (int kt = 0; kt < NT; kt++) {
        CP_WAIT0();
        __syncthreads();
        if (kt + 1 < NT) {
            int s = (kt + 1) & 1;
            const float* Ak = A + (size_t)(kt + 1) * 32;
            const float* Wk2 = W + (size_t)(kt + 1) * 32;
#pragma unroll
            for (int i = 0; i < 4; i++) {
                int chunk = i * 256 + tid;
                int r = chunk >> 3, c4 = (chunk & 7) << 2;
                cpa16(&As[((size_t)s * 128 + r) * GSTR + c4], Ak + (size_t)(rowBase + r) * K + c4);
                cpa16(&Bs[((size_t)s * 128 + r) * GSTR + c4], Wk2 + (size_t)(colOff + r) * K + c4);
            }
            CP_COMMIT();
        }
        const float* Ac = As + (size_t)(kt & 1) * 128 * GSTR;
        const float* Bc = Bs + (size_t)(kt & 1) * 128 * GSTR;
#pragma unroll
        for (int kk = 0; kk < 32; kk += 8) {
            unsigned a[4][4], b[4][2];
#pragma unroll
            for (int mt = 0; mt < 4; mt++) {
                int r = wm * 64 + mt * 16;
                a[mt][0] = f2tf32(Ac[(r + g) * GSTR + kk + t]);
                a[mt][1] = f2tf32(Ac[(r + g + 8) * GSTR + kk + t]);
                a[mt][2] = f2tf32(Ac[(r + g) * GSTR + kk + t + 4]);
                a[mt][3] = f2tf32(Ac[(r + g + 8) * GSTR + kk + t + 4]);
            }
#pragma unroll
            for (int nt = 0; nt < 4; nt++) {
                int c = wn * 32 + nt * 8 + g;
                b[nt][0] = f2tf32(Bc[c * GSTR + kk + t]);
                b[nt][1] = f2tf32(Bc[c * GSTR + kk + t + 4]);
            }
#pragma unroll
            for (int mt = 0; mt < 4; mt++)
#pragma unroll
                for (int nt = 0; nt < 4; nt++)
                    mma_tf32(acc[mt][nt], a[mt], b[nt]);
        }
        __syncthreads();
    }

    // epilogue
#pragma unroll
    for (int mt = 0; mt < 4; mt++) {
#pragma unroll
        for (int nt = 0; nt < 4; nt++) {
            int colL = colOff + wn * 32 + nt * 8 + 2 * t;   // local col within region
            float b0 = bias[colL], b1 = bias[colL + 1];
#pragma unroll
            for (int half = 0; half < 2; half++) {
                int row = rowBase + wm * 64 + mt * 16 + g + half * 8;
                float v0 = acc[mt][nt][half * 2 + 0] + b0;
                float v1 = acc[mt][nt][half * 2 + 1] + b1;
                if (mode == 0) {
                    size_t base = (size_t)row * 2048 + colL;
                    outP[base] = v0; outP[base + 1] = v1;
                } else {
                    int b_ = row >> 11, s_ = row & (SEQC - 1);
                    int h0 = colL >> 7, d0 = colL & (D_HEADC - 1);
                    size_t o0 = (((size_t)(b_ * H + h0)) * SEQC + s_) * D_HEADC + d0;
                    outP[o0] = v0; outP[o0 + 1] = v1;
                }
            }
        }
    }
}

// ---------------- flash attention (tf32, 256 thr, 128-row Q tile in regs) ----------------
#define FSTR 132   // 128 + 4
#define PSTR 68    // 64 + 4
// smem: K[2][64][FSTR] + V[2][64][FSTR] + P[8][16][PSTR]
#define FLASH_SMEM ((4*64*FSTR + 8*16*PSTR) * 4)   // 169984 B

__global__ __launch_bounds__(256)
void flash_kernel(const int* __restrict__ mask) {
    extern __shared__ float sh[];
    float* Ks = sh;                       // [2][64][FSTR]
    float* Vs = Ks + 2 * 64 * FSTR;       // [2][64][FSTR]
    float* Ps = Vs + 2 * 64 * FSTR;       // [8][16][PSTR]

    const int qt = blockIdx.x, h = blockIdx.y, b = blockIdx.z;
    const int kh = h >> 2;                // N_REP = 4
    const int tid = threadIdx.x;
    const int warp = tid >> 5, lane = tid & 31;   // 8 warps x 16 q-rows
    const int g = lane >> 2, t = lane & 3;
    float* Pw = Ps + warp * 16 * PSTR;

    const float QSCALE = 0.088388347648318447f * 1.4426950408889634f; // (1/sqrt(128))*log2(e)
    const float* Qg = g_Q + (((size_t)(b * N_HEADC + h)) * SEQC + qt * 128) * D_HEADC;
    const float* Kg = g_K + (((size_t)(b * N_KVC + kh)) * SEQC) * D_HEADC;
    const float* Vg = g_V + (((size_t)(b * N_KVC + kh)) * SEQC) * D_HEADC;

    // ---- stage Q (128x128) through the K double-buffer, grab fragments ----
#pragma unroll
    for (int i = 0; i < 16; i++) {
        int chunk = i * 256 + tid;        // 4096 float4 chunks
        int r = chunk >> 5;
        int c4 = (chunk & 31) << 2;
        float4 v = *reinterpret_cast<const float4*>(Qg + (size_t)r * D_HEADC + c4);
        *reinterpret_cast<float4*>(&Ks[r * FSTR + c4]) = v;
    }
    __syncthreads();

    unsigned qa[16][4];                   // Q fragments, whole d=128
    const int qr = warp * 16;
#pragma unroll
    for (int ks = 0; ks < 16; ks++) {
        int kb = ks * 8;
        qa[ks][0] = f2tf32(Ks[(qr + g) * FSTR + kb + t] * QSCALE);
        qa[ks][1] = f2tf32(Ks[(qr + g + 8) * FSTR + kb + t] * QSCALE);
        qa[ks][2] = f2tf32(Ks[(qr + g) * FSTR + kb + t + 4] * QSCALE);
        qa[ks][3] = f2tf32(Ks[(qr + g + 8) * FSTR + kb + t + 4] * QSCALE);
    }
    __syncthreads();                      // all Q reads done before cp.async overwrites Ks

    // ---- prologue: K/V tile 0 -> stage 0 ----
    {
#pragma unroll
        for (int i = 0; i < 8; i++) {
            int chunk = i * 256 + tid;    // 2048 float4 chunks per tile
            int r = chunk >> 5, c4 = (chunk & 31) << 2;
            cpa16(&Ks[r * FSTR + c4], Kg + (size_t)r * D_HEADC + c4);
            cpa16(&Vs[r * FSTR + c4], Vg + (size_t)r * D_HEADC + c4);
        }
        CP_COMMIT();
    }

    float m0 = -1e30f, m1 = -1e30f, l0 = 0.f, l1 = 0.f;
    float o[16][4];
#pragma unroll
    for (int i = 0; i < 16; i++)
#pragma unroll
        for (int j = 0; j < 4; j++) o[i][j] = 0.f;

    const int qflag = qt * 2 + (warp >> 2);    // 64-row flag tile for this warp

    for (int kt = 0; kt < 32; kt++) {
        CP_WAIT0();
        __syncthreads();
        if (kt + 1 < 32) {
            int s = (kt + 1) & 1;
            const float* Kt = Kg + (size_t)(kt + 1) * 64 * D_HEADC;
            const float* Vt = Vg + (size_t)(kt + 1) * 64 * D_HEADC;
#pragma unroll
            for (int i = 0; i < 8; i++) {
                int chunk = i * 256 + tid;
                int r = chunk >> 5, c4 = (chunk & 31) << 2;
                cpa16(&Ks[((size_t)s * 64 + r) * FSTR + c4], Kt + (size_t)r * D_HEADC + c4);
                cpa16(&Vs[((size_t)s * 64 + r) * FSTR + c4], Vt + (size_t)r * D_HEADC + c4);
            }
            CP_COMMIT();
        }
        const float* Kc = Ks + (size_t)(kt & 1) * 64 * FSTR;
        const float* Vc = Vs + (size_t)(kt & 1) * 64 * FSTR;

        // S = Q * K^T
        float s[8][4];
#pragma unroll
        for (int i = 0; i < 8; i++)
#pragma unroll
            for (int j = 0; j < 4; j++) s[i][j] = 0.f;
#pragma unroll
        for (int ks = 0; ks < 16; ks++) {
            int kb = ks * 8;
#pragma unroll
            for (int nt = 0; nt < 8; nt++) {
                unsigned bb[2];
                bb[0] = f2tf32(Kc[(nt * 8 + g) * FSTR + kb + t]);
                bb[1] = f2tf32(Kc[(nt * 8 + g) * FSTR + kb + t + 4]);
                mma_tf32(s[nt], qa[ks], bb);
            }
        }

        // masking (fast path: skip when 64x64 tile is all ones)
        if (g_flags[(b * 32 + qflag) * 32 + kt]) {
            int qr0 = qt * 128 + warp * 16 + g;
            const int* mrow0 = mask + ((size_t)b * SEQC + qr0) * SEQC;
            const int* mrow1 = mrow0 + 8 * SEQC;
#pragma unroll
            for (int nt = 0; nt < 8; nt++) {
                int kc = kt * 64 + nt * 8 + 2 * t;
                if (mrow0[kc] == 0)     s[nt][0] = -1e30f;
                if (mrow0[kc + 1] == 0) s[nt][1] = -1e30f;
                if (mrow1[kc] == 0)     s[nt][2] = -1e30f;
                if (mrow1[kc + 1] == 0) s[nt][3] = -1e30f;
            }
        }

        // online softmax (base 2)
        float mx0 = -1e30f, mx1 = -1e30f;
#pragma unroll
        for (int nt = 0; nt < 8; nt++) {
            mx0 = fmaxf(mx0, fmaxf(s[nt][0], s[nt][1]));
            mx1 = fmaxf(mx1, fmaxf(s[nt][2], s[nt][3]));
        }
        mx0 = fmaxf(mx0, __shfl_xor_sync(0xffffffffu, mx0, 1));
        mx0 = fmaxf(mx0, __shfl_xor_sync(0xffffffffu, mx0, 2));
        mx1 = fmaxf(mx1, __shfl_xor_sync(0xffffffffu, mx1, 1));
        mx1 = fmaxf(mx1, __shfl_xor_sync(0xffffffffu, mx1, 2));
        float nm0 = fmaxf(m0, mx0), nm1 = fmaxf(m1, mx1);
        float c0 = ex2(m0 - nm0), c1 = ex2(m1 - nm1);
        m0 = nm0; m1 = nm1;

        float ps0 = 0.f, ps1 = 0.f;
#pragma unroll
        for (int nt = 0; nt < 8; nt++) {
            float p00 = ex2(s[nt][0] - nm0);
            float p01 = ex2(s[nt][1] - nm0);
            float p10 = ex2(s[nt][2] - nm1);
            float p11 = ex2(s[nt][3] - nm1);
            ps0 += p00 + p01;
            ps1 += p10 + p11;
            int col = nt * 8 + 2 * t;
            Pw[g * PSTR + col]           = __uint_as_float(f2tf32(p00));
            Pw[g * PSTR + col + 1]       = __uint_as_float(f2tf32(p01));
            Pw[(g + 8) * PSTR + col]     = __uint_as_float(f2tf32(p10));
            Pw[(g + 8) * PSTR + col + 1] = __uint_as_float(f2tf32(p11));
        }
        ps0 += __shfl_xor_sync(0xffffffffu, ps0, 1);
        ps0 += __shfl_xor_sync(0xffffffffu, ps0, 2);
        ps1 += __shfl_xor_sync(0xffffffffu, ps1, 1);
        ps1 += __shfl_xor_sync(0xffffffffu, ps1, 2);
        l0 = l0 * c0 + ps0;
        l1 = l1 * c1 + ps1;
#pragma unroll
        for (int nt = 0; nt < 16; nt++) {
            o[nt][0] *= c0; o[nt][1] *= c0;
            o[nt][2] *= c1; o[nt][3] *= c1;
        }
        __syncwarp();

        // O += P * V
#pragma unroll
        for (int ks = 0; ks < 8; ks++) {
            int kb = ks * 8;
            unsigned a[4];
            a[0] = __float_as_uint(Pw[g * PSTR + kb + t]);
            a[1] = __float_as_uint(Pw[(g + 8) * PSTR + kb + t]);
            a[2] = __float_as_uint(Pw[g * PSTR + kb + t + 4]);
            a[3] = __float_as_uint(Pw[(g + 8) * PSTR + kb + t + 4]);
#pragma unroll
            for (int nt = 0; nt < 16; nt++) {
                unsigned bb[2];
                bb[0] = f2tf32(Vc[(kb + t) * FSTR + nt * 8 + g]);
                bb[1] = f2tf32(Vc[(kb + t + 4) * FSTR + nt * 8 + g]);
                mma_tf32(o[nt], a, bb);
            }
        }
    }

    // epilogue: normalize + write to [b,s,h,d]
    float inv0 = 1.0f / l0, inv1 = 1.0f / l1;
    int s0 = qt * 128 + warp * 16 + g;
#pragma unroll
    for (int nt = 0; nt < 16; nt++) {
        int d0 = nt * 8 + 2 * t;
        size_t base0 = (((size_t)b * SEQC + s0) * N_HEADC + h) * D_HEADC + d0;
        size_t base1 = (((size_t)b * SEQC + s0 + 8) * N_HEADC + h) * D_HEADC + d0;
        g_AO[base0] = o[nt][0] * inv0; g_AO[base0 + 1] = o[nt][1] * inv0;
        g_AO[base1] = o[nt][2] * inv1; g_AO[base1 + 1] = o[nt][3] * inv1;
    }
}

// ---------------- launch ----------------
extern "C" void kernel_launch(void* const* d_in, const int* in_sizes, int n_in,
                              void* d_out, int out_size) {
    const float* hidden = (const float*)d_in[0];
    const int*   mask   = (const int*)d_in[1];
    const float* Wq = (const float*)d_in[2];
    const float* bq = (const float*)d_in[3];
    const float* Wk = (const float*)d_in[4];
    const float* bk = (const float*)d_in[5];
    const float* Wv = (const float*)d_in[6];
    const float* bv = (const float*)d_in[7];
    const float* Wo = (const float*)d_in[8];
    const float* bo = (const float*)d_in[9];
    float* out = (float*)d_out;

    void *pQ, *pK, *pV, *pAO;
    cudaGetSymbolAddress(&pQ, g_Q);
    cudaGetSymbolAddress(&pK, g_K);
    cudaGetSymbolAddress(&pV, g_V);
    cudaGetSymbolAddress(&pAO, g_AO);

    cudaFuncSetAttribute(gemm_pipe_kernel, cudaFuncAttributeMaxDynamicSharedMemorySize, GEMM_SMEM);
    cudaFuncSetAttribute(flash_kernel, cudaFuncAttributeMaxDynamicSharedMemorySize, FLASH_SMEM);

    mask_scan_kernel<<<dim3(32, 32, BATCHC), 128>>>(mask);
    // fused QKV projection
    gemm_pipe_kernel<<<dim3(24, M_ROWS / 128), 256, GEMM_SMEM>>>(
        hidden, Wq, bq, Wk, bk, Wv, bv, (float*)pQ, (float*)pK, (float*)pV, 1);
    flash_kernel<<<dim3(16, N_HEADC, BATCHC), 256, FLASH_SMEM>>>(mask);
    // O projection
    gemm_pipe_kernel<<<dim3(16, M_ROWS / 128), 256, GEMM_SMEM>>>(
        (const float*)pAO, Wo, bo, Wo, bo, Wo, bo, out, out, out, 0);
}

// round 6
// speedup vs baseline: 1.5647x; 1.0698x over previous
#include <cuda_runtime.h>
#include <cstdint>

#define N_HEADC 16
#define N_KVC 4
#define D_MODELC 2048
#define D_HEADC 128
#define BATCHC 2
#define SEQC 2048
#define M_ROWS (BATCHC*SEQC)           // 4096
#define Q_INNERC (N_HEADC*D_HEADC)     // 2048
#define KV_INNERC (N_KVC*D_HEADC)      // 512
#define QSCALE_F (0.088388347648318447f * 1.4426950408889634f)   // (1/sqrt(128))*log2(e)

// ---------------- scratch (device globals: allocation-free) ----------------
__device__ float g_Q[(size_t)BATCHC*N_HEADC*SEQC*D_HEADC];   // [b,h,s,d] tf32 bits, pre-scaled
__device__ float g_K[(size_t)BATCHC*N_KVC*SEQC*D_HEADC];     // [b,kh,s,d] tf32 bits
__device__ float g_V[(size_t)BATCHC*N_KVC*SEQC*D_HEADC];     // tf32 bits
__device__ float g_AO[(size_t)M_ROWS*Q_INNERC];              // [b,s,h,d] tf32 bits
__device__ float g_H [(size_t)M_ROWS*D_MODELC];              // hidden, tf32 bits
__device__ float g_Wq[(size_t)Q_INNERC*D_MODELC];            // weights, tf32 bits
__device__ float g_Wk[(size_t)KV_INNERC*D_MODELC];
__device__ float g_Wv[(size_t)KV_INNERC*D_MODELC];
__device__ float g_Wo[(size_t)D_MODELC*Q_INNERC];
__device__ int   g_flags[BATCHC*32*32];                      // per 64x64 mask tile: any-zero?

// ---------------- helpers ----------------
__device__ __forceinline__ unsigned f2tf32(float x) {
    unsigned u;
    asm("cvt.rna.tf32.f32 %0, %1;" : "=r"(u) : "f"(x));
    return u;
}
__device__ __forceinline__ float ex2(float x) {
    float y;
    asm("ex2.approx.f32 %0, %1;" : "=f"(y) : "f"(x));
    return y;
}
__device__ __forceinline__ void mma_tf32(float* d, const unsigned* a, const unsigned* b) {
    asm volatile(
        "mma.sync.aligned.m16n8k8.row.col.f32.tf32.tf32.f32 "
        "{%0,%1,%2,%3}, {%4,%5,%6,%7}, {%8,%9}, {%0,%1,%2,%3};"
        : "+f"(d[0]), "+f"(d[1]), "+f"(d[2]), "+f"(d[3])
        : "r"(a[0]), "r"(a[1]), "r"(a[2]), "r"(a[3]), "r"(b[0]), "r"(b[1]));
}
__device__ __forceinline__ void cpa16(float* dst_smem, const float* src) {
    unsigned d = (unsigned)__cvta_generic_to_shared(dst_smem);
    asm volatile("cp.async.cg.shared.global [%0], [%1], 16;\n" :: "r"(d), "l"(src));
}
#define CP_COMMIT() asm volatile("cp.async.commit_group;\n" ::: "memory")
#define CP_WAIT0()  asm volatile("cp.async.wait_group 0;\n" ::: "memory")

// ---------------- tf32 pre-conversion ----------------
__global__ __launch_bounds__(256)
void cvt_kernel(const float* __restrict__ src, float* __restrict__ dst, int n4) {
    int i = blockIdx.x * blockDim.x + threadIdx.x;
    for (; i < n4; i += gridDim.x * blockDim.x) {
        float4 v = reinterpret_cast<const float4*>(src)[i];
        v.x = __uint_as_float(f2tf32(v.x));
        v.y = __uint_as_float(f2tf32(v.y));
        v.z = __uint_as_float(f2tf32(v.z));
        v.w = __uint_as_float(f2tf32(v.w));
        reinterpret_cast<float4*>(dst)[i] = v;
    }
}

// ---------------- mask tile prepass ----------------
__global__ __launch_bounds__(128)
void mask_scan_kernel(const int* __restrict__ mask) {
    const int kt = blockIdx.x, qt = blockIdx.y, b = blockIdx.z;
    const int tid = threadIdx.x;
    int any0 = 0;
#pragma unroll
    for (int i = 0; i < 8; i++) {
        int idx = i * 128 + tid;
        int r = idx >> 4;
        int c4 = (idx & 15) << 2;
        const int4 v = *reinterpret_cast<const int4*>(
            mask + ((size_t)b * SEQC + qt * 64 + r) * SEQC + kt * 64 + c4);
        if (!(v.x && v.y && v.z && v.w)) any0 = 1;
    }
    any0 = __syncthreads_or(any0);
    if (tid == 0) g_flags[(b * 32 + qt) * 32 + kt] = any0;
}

// ---------------- pipelined tf32 GEMM (cp.async, no in-loop cvt) ----------------
// mode 1: fused QKV. blockIdx.x 0-15 -> Q (pre-scaled), 16-19 -> K, 20-23 -> V; tf32-bit out.
// mode 0: O proj. out row-major [M, 2048], plain fp32.
#define GSTR 36
#define GEMM_SMEM (2*2*128*GSTR*4)   // 73728 B

__global__ __launch_bounds__(256, 2)
void gemm_pipe_kernel(const float* __restrict__ A,
                      const float* __restrict__ Wq, const float* __restrict__ bq,
                      const float* __restrict__ Wk, const float* __restrict__ bk,
                      const float* __restrict__ Wv, const float* __restrict__ bv,
                      float* outQ, float* outK, float* outV, int mode) {
    extern __shared__ float sm[];
    float* As = sm;                    // [2][128][GSTR]
    float* Bs = sm + 2 * 128 * GSTR;   // [2][128][GSTR]

    const int tid = threadIdx.x;
    const int warp = tid >> 5, lane = tid & 31;
    const int g = lane >> 2, t = lane & 3;
    const int wm = warp >> 2, wn = warp & 3;       // 2x4 warps: 64x32 tiles
    const int rowBase = blockIdx.y * 128;
    const int bx = blockIdx.x;

    const float* W; const float* bias; float* outP; int colOff; int H;
    if (mode == 0)       { W = Wq; bias = bq; outP = outQ; colOff = bx * 128;        H = 0;  }
    else if (bx < 16)    { W = Wq; bias = bq; outP = outQ; colOff = bx * 128;        H = 16; }
    else if (bx < 20)    { W = Wk; bias = bk; outP = outK; colOff = (bx - 16) * 128; H = 4;  }
    else                 { W = Wv; bias = bv; outP = outV; colOff = (bx - 20) * 128; H = 4;  }

    const int K = D_MODELC;
    const int NT = K / 32;

    float acc[4][4][4];
#pragma unroll
    for (int i = 0; i < 4; i++)
#pragma unroll
        for (int j = 0; j < 4; j++)
#pragma unroll
            for (int q = 0; q < 4; q++) acc[i][j][q] = 0.f;

    // prologue: stage 0
    {
#pragma unroll
        for (int i = 0; i < 4; i++) {
            int chunk = i * 256 + tid;         // 1024 chunks of 16B
            int r = chunk >> 3, c4 = (chunk & 7) << 2;
            cpa16(&As[(size_t)r * GSTR + c4], A + (size_t)(rowBase + r) * K + c4);
            cpa16(&Bs[(size_t)r * GSTR + c4], W + (size_t)(colOff + r) * K + c4);
        }
        CP_COMMIT();
    }

    for (int kt = 0; kt < NT; kt++) {
        CP_WAIT0();
        __syncthreads();
        if (kt + 1 < NT) {
            int s = (kt + 1) & 1;
            const float* Ak = A + (size_t)(kt + 1) * 32;
            const float* Wk2 = W + (size_t)(kt + 1) * 32;
#pragma unroll
            for (int i = 0; i < 4; i++) {
                int chunk = i * 256 + tid;
                int r = chunk >> 3, c4 = (chunk & 7) << 2;
                cpa16(&As[((size_t)s * 128 + r) * GSTR + c4], Ak + (size_t)(rowBase + r) * K + c4);
                cpa16(&Bs[((size_t)s * 128 + r) * GSTR + c4], Wk2 + (size_t)(colOff + r) * K + c4);
            }
            CP_COMMIT();
        }
        const float* Ac = As + (size_t)(kt & 1) * 128 * GSTR;
        const float* Bc = Bs + (size_t)(kt & 1) * 128 * GSTR;
#pragma unroll
        for (int kk = 0; kk < 32; kk += 8) {
            unsigned a[4][4], b[4][2];
#pragma unroll
            for (int mt = 0; mt < 4; mt++) {
                int r = wm * 64 + mt * 16;
                a[mt][0] = __float_as_uint(Ac[(r + g) * GSTR + kk + t]);
                a[mt][1] = __float_as_uint(Ac[(r + g + 8) * GSTR + kk + t]);
                a[mt][2] = __float_as_uint(Ac[(r + g) * GSTR + kk + t + 4]);
                a[mt][3] = __float_as_uint(Ac[(r + g + 8) * GSTR + kk + t + 4]);
            }
#pragma unroll
            for (int nt = 0; nt < 4; nt++) {
                int c = wn * 32 + nt * 8 + g;
                b[nt][0] = __float_as_uint(Bc[c * GSTR + kk + t]);
                b[nt][1] = __float_as_uint(Bc[c * GSTR + kk + t + 4]);
            }
#pragma unroll
            for (int mt = 0; mt < 4; mt++)
#pragma unroll
                for (int nt = 0; nt < 4; nt++)
                    mma_tf32(acc[mt][nt], a[mt], b[nt]);
        }
        __syncthreads();
    }

    // epilogue
    const float scaleQ = (mode == 1 && H == 16) ? QSCALE_F : 1.0f;
#pragma unroll
    for (int mt = 0; mt < 4; mt++) {
#pragma unroll
        for (int nt = 0; nt < 4; nt++) {
            int colL = colOff + wn * 32 + nt * 8 + 2 * t;
            float b0 = bias[colL], b1 = bias[colL + 1];
#pragma unroll
            for (int half = 0; half < 2; half++) {
                int row = rowBase + wm * 64 + mt * 16 + g + half * 8;
                float v0 = acc[mt][nt][half * 2 + 0] + b0;
                float v1 = acc[mt][nt][half * 2 + 1] + b1;
                if (mode == 0) {
                    size_t base = (size_t)row * 2048 + colL;
                    outP[base] = v0; outP[base + 1] = v1;
                } else {
                    int b_ = row >> 11, s_ = row & (SEQC - 1);
                    int h0 = colL >> 7, d0 = colL & (D_HEADC - 1);
                    size_t o0 = (((size_t)(b_ * H + h0)) * SEQC + s_) * D_HEADC + d0;
                    outP[o0]     = __uint_as_float(f2tf32(v0 * scaleQ));
                    outP[o0 + 1] = __uint_as_float(f2tf32(v1 * scaleQ));
                }
            }
        }
    }
}

// ---------------- flash attention (tf32 bits in, 256 thr, 128-row Q tile in regs) ----------------
#define FSTR 132   // 128 + 4
#define PSTR 68    // 64 + 4
// smem: K[2][64][FSTR] + V[2][64][FSTR] + P[8][16][PSTR]
#define FLASH_SMEM ((4*64*FSTR + 8*16*PSTR) * 4)   // 169984 B

__global__ __launch_bounds__(256)
void flash_kernel(const int* __restrict__ mask) {
    extern __shared__ float sh[];
    float* Ks = sh;                       // [2][64][FSTR]
    float* Vs = Ks + 2 * 64 * FSTR;       // [2][64][FSTR]
    float* Ps = Vs + 2 * 64 * FSTR;       // [8][16][PSTR]

    const int qt = blockIdx.x, h = blockIdx.y, b = blockIdx.z;
    const int kh = h >> 2;                // N_REP = 4
    const int tid = threadIdx.x;
    const int warp = tid >> 5, lane = tid & 31;   // 8 warps x 16 q-rows
    const int g = lane >> 2, t = lane & 3;
    float* Pw = Ps + warp * 16 * PSTR;

    const float* Qg = g_Q + (((size_t)(b * N_HEADC + h)) * SEQC + qt * 128) * D_HEADC;
    const float* Kg = g_K + (((size_t)(b * N_KVC + kh)) * SEQC) * D_HEADC;
    const float* Vg = g_V + (((size_t)(b * N_KVC + kh)) * SEQC) * D_HEADC;

    // ---- stage Q (128x128, already tf32 bits + scale) through K buffer ----
#pragma unroll
    for (int i = 0; i < 16; i++) {
        int chunk = i * 256 + tid;        // 4096 float4 chunks
        int r = chunk >> 5;
        int c4 = (chunk & 31) << 2;
        float4 v = *reinterpret_cast<const float4*>(Qg + (size_t)r * D_HEADC + c4);
        *reinterpret_cast<float4*>(&Ks[r * FSTR + c4]) = v;
    }
    __syncthreads();

    unsigned qa[16][4];                   // Q fragments, whole d=128
    const int qr = warp * 16;
#pragma unroll
    for (int ks = 0; ks < 16; ks++) {
        int kb = ks * 8;
        qa[ks][0] = __float_as_uint(Ks[(qr + g) * FSTR + kb + t]);
        qa[ks][1] = __float_as_uint(Ks[(qr + g + 8) * FSTR + kb + t]);
        qa[ks][2] = __float_as_uint(Ks[(qr + g) * FSTR + kb + t + 4]);
        qa[ks][3] = __float_as_uint(Ks[(qr + g + 8) * FSTR + kb + t + 4]);
    }
    __syncthreads();                      // all Q reads done before cp.async overwrites Ks

    // ---- prologue: K/V tile 0 -> stage 0 ----
    {
#pragma unroll
        for (int i = 0; i < 8; i++) {
            int chunk = i * 256 + tid;    // 2048 float4 chunks per tile
            int r = chunk >> 5, c4 = (chunk & 31) << 2;
            cpa16(&Ks[r * FSTR + c4], Kg + (size_t)r * D_HEADC + c4);
            cpa16(&Vs[r * FSTR + c4], Vg + (size_t)r * D_HEADC + c4);
        }
        CP_COMMIT();
    }

    float m0 = -1e30f, m1 = -1e30f, l0 = 0.f, l1 = 0.f;
    float o[16][4];
#pragma unroll
    for (int i = 0; i < 16; i++)
#pragma unroll
        for (int j = 0; j < 4; j++) o[i][j] = 0.f;

    const int qflag = qt * 2 + (warp >> 2);    // 64-row flag tile for this warp

    for (int kt = 0; kt < 32; kt++) {
        CP_WAIT0();
        __syncthreads();
        if (kt + 1 < 32) {
            int s = (kt + 1) & 1;
            const float* Kt = Kg + (size_t)(kt + 1) * 64 * D_HEADC;
            const float* Vt = Vg + (size_t)(kt + 1) * 64 * D_HEADC;
#pragma unroll
            for (int i = 0; i < 8; i++) {
                int chunk = i * 256 + tid;
                int r = chunk >> 5, c4 = (chunk & 31) << 2;
                cpa16(&Ks[((size_t)s * 64 + r) * FSTR + c4], Kt + (size_t)r * D_HEADC + c4);
                cpa16(&Vs[((size_t)s * 64 + r) * FSTR + c4], Vt + (size_t)r * D_HEADC + c4);
            }
            CP_COMMIT();
        }
        const float* Kc = Ks + (size_t)(kt & 1) * 64 * FSTR;
        const float* Vc = Vs + (size_t)(kt & 1) * 64 * FSTR;

        // S = Q * K^T  (operands are tf32 bits)
        float s[8][4];
#pragma unroll
        for (int i = 0; i < 8; i++)
#pragma unroll
            for (int j = 0; j < 4; j++) s[i][j] = 0.f;
#pragma unroll
        for (int ks = 0; ks < 16; ks++) {
            int kb = ks * 8;
#pragma unroll
            for (int nt = 0; nt < 8; nt++) {
                unsigned bb[2];
                bb[0] = __float_as_uint(Kc[(nt * 8 + g) * FSTR + kb + t]);
                bb[1] = __float_as_uint(Kc[(nt * 8 + g) * FSTR + kb + t + 4]);
                mma_tf32(s[nt], qa[ks], bb);
            }
        }

        // masking (fast path: skip when 64x64 tile is all ones)
        if (g_flags[(b * 32 + qflag) * 32 + kt]) {
            int qr0 = qt * 128 + warp * 16 + g;
            const int* mrow0 = mask + ((size_t)b * SEQC + qr0) * SEQC;
            const int* mrow1 = mrow0 + 8 * SEQC;
#pragma unroll
            for (int nt = 0; nt < 8; nt++) {
                int kc = kt * 64 + nt * 8 + 2 * t;
                if (mrow0[kc] == 0)     s[nt][0] = -1e30f;
                if (mrow0[kc + 1] == 0) s[nt][1] = -1e30f;
                if (mrow1[kc] == 0)     s[nt][2] = -1e30f;
                if (mrow1[kc + 1] == 0) s[nt][3] = -1e30f;
            }
        }

        // online softmax (base 2)
        float mx0 = -1e30f, mx1 = -1e30f;
#pragma unroll
        for (int nt = 0; nt < 8; nt++) {
            mx0 = fmaxf(mx0, fmaxf(s[nt][0], s[nt][1]));
            mx1 = fmaxf(mx1, fmaxf(s[nt][2], s[nt][3]));
        }
        mx0 = fmaxf(mx0, __shfl_xor_sync(0xffffffffu, mx0, 1));
        mx0 = fmaxf(mx0, __shfl_xor_sync(0xffffffffu, mx0, 2));
        mx1 = fmaxf(mx1, __shfl_xor_sync(0xffffffffu, mx1, 1));
        mx1 = fmaxf(mx1, __shfl_xor_sync(0xffffffffu, mx1, 2));
        float nm0 = fmaxf(m0, mx0), nm1 = fmaxf(m1, mx1);
        float c0 = ex2(m0 - nm0), c1 = ex2(m1 - nm1);
        m0 = nm0; m1 = nm1;

        float ps0 = 0.f, ps1 = 0.f;
#pragma unroll
        for (int nt = 0; nt < 8; nt++) {
            float p00 = ex2(s[nt][0] - nm0);
            float p01 = ex2(s[nt][1] - nm0);
            float p10 = ex2(s[nt][2] - nm1);
            float p11 = ex2(s[nt][3] - nm1);
            ps0 += p00 + p01;
            ps1 += p10 + p11;
            int col = nt * 8 + 2 * t;
            Pw[g * PSTR + col]           = __uint_as_float(f2tf32(p00));
            Pw[g * PSTR + col + 1]       = __uint_as_float(f2tf32(p01));
            Pw[(g + 8) * PSTR + col]     = __uint_as_float(f2tf32(p10));
            Pw[(g + 8) * PSTR + col + 1] = __uint_as_float(f2tf32(p11));
        }
        ps0 += __shfl_xor_sync(0xffffffffu, ps0, 1);
        ps0 += __shfl_xor_sync(0xffffffffu, ps0, 2);
        ps1 += __shfl_xor_sync(0xffffffffu, ps1, 1);
        ps1 += __shfl_xor_sync(0xffffffffu, ps1, 2);
        l0 = l0 * c0 + ps0;
        l1 = l1 * c1 + ps1;
#pragma unroll
        for (int nt = 0; nt < 16; nt++) {
            o[nt][0] *= c0; o[nt][1] *= c0;
            o[nt][2] *= c1; o[nt][3] *= c1;
        }
        __syncwarp();

        // O += P * V
#pragma unroll
        for (int ks = 0; ks < 8; ks++) {
            int kb = ks * 8;
            unsigned a[4];
            a[0] = __float_as_uint(Pw[g * PSTR + kb + t]);
            a[1] = __float_as_uint(Pw[(g + 8) * PSTR + kb + t]);
            a[2] = __float_as_uint(Pw[g * PSTR + kb + t + 4]);
            a[3] = __float_as_uint(Pw[(g + 8) * PSTR + kb + t + 4]);
#pragma unroll
            for (int nt = 0; nt < 16; nt++) {
                unsigned bb[2];
                bb[0] = __float_as_uint(Vc[(kb + t) * FSTR + nt * 8 + g]);
                bb[1] = __float_as_uint(Vc[(kb + t + 4) * FSTR + nt * 8 + g]);
                mma_tf32(o[nt], a, bb);
            }
        }
    }

    // epilogue: normalize + write tf32 bits to [b,s,h,d]
    float inv0 = 1.0f / l0, inv1 = 1.0f / l1;
    int s0 = qt * 128 + warp * 16 + g;
#pragma unroll
    for (int nt = 0; nt < 16; nt++) {
        int d0 = nt * 8 + 2 * t;
        size_t base0 = (((size_t)b * SEQC + s0) * N_HEADC + h) * D_HEADC + d0;
        size_t base1 = (((size_t)b * SEQC + s0 + 8) * N_HEADC + h) * D_HEADC + d0;
        g_AO[base0]     = __uint_as_float(f2tf32(o[nt][0] * inv0));
        g_AO[base0 + 1] = __uint_as_float(f2tf32(o[nt][1] * inv0));
        g_AO[base1]     = __uint_as_float(f2tf32(o[nt][2] * inv1));
        g_AO[base1 + 1] = __uint_as_float(f2tf32(o[nt][3] * inv1));
    }
}

// ---------------- launch ----------------
extern "C" void kernel_launch(void* const* d_in, const int* in_sizes, int n_in,
                              void* d_out, int out_size) {
    const float* hidden = (const float*)d_in[0];
    const int*   mask   = (const int*)d_in[1];
    const float* Wq = (const float*)d_in[2];
    const float* bq = (const float*)d_in[3];
    const float* Wk = (const float*)d_in[4];
    const float* bk = (const float*)d_in[5];
    const float* Wv = (const float*)d_in[6];
    const float* bv = (const float*)d_in[7];
    const float* Wo = (const float*)d_in[8];
    const float* bo = (const float*)d_in[9];
    float* out = (float*)d_out;

    void *pQ, *pK, *pV, *pAO, *pH, *pWq, *pWk, *pWv, *pWo;
    cudaGetSymbolAddress(&pQ, g_Q);
    cudaGetSymbolAddress(&pK, g_K);
    cudaGetSymbolAddress(&pV, g_V);
    cudaGetSymbolAddress(&pAO, g_AO);
    cudaGetSymbolAddress(&pH, g_H);
    cudaGetSymbolAddress(&pWq, g_Wq);
    cudaGetSymbolAddress(&pWk, g_Wk);
    cudaGetSymbolAddress(&pWv, g_Wv);
    cudaGetSymbolAddress(&pWo, g_Wo);

    cudaFuncSetAttribute(gemm_pipe_kernel, cudaFuncAttributeMaxDynamicSharedMemorySize, GEMM_SMEM);
    cudaFuncSetAttribute(flash_kernel, cudaFuncAttributeMaxDynamicSharedMemorySize, FLASH_SMEM);

    // tf32 pre-conversion prepass
    cvt_kernel<<<512, 256>>>(hidden, (float*)pH,  (int)((size_t)M_ROWS * D_MODELC / 4));
    cvt_kernel<<<512, 256>>>(Wq,     (float*)pWq, (int)((size_t)Q_INNERC * D_MODELC / 4));
    cvt_kernel<<<256, 256>>>(Wk,     (float*)pWk, (int)((size_t)KV_INNERC * D_MODELC / 4));
    cvt_kernel<<<256, 256>>>(Wv,     (float*)pWv, (int)((size_t)KV_INNERC * D_MODELC / 4));
    cvt_kernel<<<512, 256>>>(Wo,     (float*)pWo, (int)((size_t)D_MODELC * Q_INNERC / 4));

    mask_scan_kernel<<<dim3(32, 32, BATCHC), 128>>>(mask);
    // fused QKV projection (emits tf32 bits; Q pre-scaled)
    gemm_pipe_kernel<<<dim3(24, M_ROWS / 128), 256, GEMM_SMEM>>>(
        (const float*)pH, (const float*)pWq, bq, (const float*)pWk, bk,
        (const float*)pWv, bv, (float*)pQ, (float*)pK, (float*)pV, 1);
    flash_kernel<<<dim3(16, N_HEADC, BATCHC), 256, FLASH_SMEM>>>(mask);
    // O projection (plain fp32 out)
    gemm_pipe_kernel<<<dim3(16, M_ROWS / 128), 256, GEMM_SMEM>>>(
        (const float*)pAO, (const float*)pWo, bo, (const float*)pWo, bo,
        (const float*)pWo, bo, out, out, out, 0);
}